// round 1
// baseline (speedup 1.0000x reference)
#include <cuda_runtime.h>

// Problem constants
#define NN_NODES 4096
#define NN_EDGES 8192
#define DIM_V    512
#define DIM_OUT  512
#define DIM_E    128

// Scratch (device globals — no allocation allowed)
__device__ float g_e_scale[NN_EDGES];
__device__ float g_Acomb[(size_t)NN_NODES * NN_NODES];   // 64 MB
__device__ float g_HW[(size_t)NN_NODES * DIM_OUT];       //  8 MB

// ---------------- packed f32x2 helpers ----------------
__device__ __forceinline__ void ffma2(unsigned long long& d,
                                      unsigned long long a,
                                      unsigned long long b) {
    asm("fma.rn.f32x2 %0, %1, %2, %0;" : "+l"(d) : "l"(a), "l"(b));
}
__device__ __forceinline__ unsigned long long pack2(float x, float y) {
    unsigned long long r;
    asm("mov.b64 %0, {%1, %2};" : "=l"(r) : "f"(x), "f"(y));
    return r;
}
__device__ __forceinline__ float2 unpack2(unsigned long long v) {
    float2 f;
    asm("mov.b64 {%0, %1}, %2;" : "=f"(f.x), "=f"(f.y) : "l"(v));
    return f;
}

// ---------------- K0: e_scale[e] = dot(H_e[e,:], p) ----------------
__global__ void escale_kernel(const float* __restrict__ He,
                              const float* __restrict__ p) {
    int row  = blockIdx.x * 8 + threadIdx.y;   // block (32,8): 8 rows/block
    int lane = threadIdx.x;
    float4 h  = ((const float4*)(He + (size_t)row * DIM_E))[lane];
    float4 pv = ((const float4*)p)[lane];
    float v = h.x * pv.x + h.y * pv.y + h.z * pv.z + h.w * pv.w;
    #pragma unroll
    for (int o = 16; o; o >>= 1) v += __shfl_xor_sync(0xffffffffu, v, o);
    if (lane == 0) g_e_scale[row] = v;
}

// ---------------- K2: GEMM1 (NT) with fused epilogue ----------------
// S = (T * e) @ T^T ; A_comb = (i==j) ? adj_v : 0.5*adj_v*(S+1)
__global__ __launch_bounds__(256, 2) void gemm1_kernel(
    const float* __restrict__ T, const float* __restrict__ adj_v) {
    __shared__ __align__(16) float As[2][8][128];
    __shared__ __align__(16) float Bs[2][8][128];

    const int K = NN_EDGES;
    const int tid = threadIdx.x;
    const int iBase = blockIdx.y * 128;
    const int jBase = blockIdx.x * 128;

    const int lrow = tid >> 1;
    const int kq   = (tid & 1) * 4;

    const float* Aptr = T + (size_t)(iBase + lrow) * K + kq;
    const float* Bptr = T + (size_t)(jBase + lrow) * K + kq;
    const float* Eptr = g_e_scale + kq;

    unsigned long long acc[8][4];
    #pragma unroll
    for (int r = 0; r < 8; ++r)
        #pragma unroll
        for (int c = 0; c < 4; ++c) acc[r][c] = 0ull;

    // prologue: tile 0
    {
        float4 a = *(const float4*)Aptr;
        float4 e = *(const float4*)Eptr;
        float4 b = *(const float4*)Bptr;
        As[0][kq + 0][lrow] = a.x * e.x;
        As[0][kq + 1][lrow] = a.y * e.y;
        As[0][kq + 2][lrow] = a.z * e.z;
        As[0][kq + 3][lrow] = a.w * e.w;
        Bs[0][kq + 0][lrow] = b.x;
        Bs[0][kq + 1][lrow] = b.y;
        Bs[0][kq + 2][lrow] = b.z;
        Bs[0][kq + 3][lrow] = b.w;
    }
    __syncthreads();

    const int tx = (tid & 15) * 8;
    const int ty = (tid >> 4) * 8;
    int buf = 0;
    const int KT = K / 8;

    for (int kt = 0; kt < KT; ++kt) {
        float4 aN, eN, bN;
        if (kt + 1 < KT) {
            aN = *(const float4*)(Aptr + (size_t)(kt + 1) * 8);
            eN = *(const float4*)(Eptr + (size_t)(kt + 1) * 8);
            bN = *(const float4*)(Bptr + (size_t)(kt + 1) * 8);
        }
        #pragma unroll
        for (int kk = 0; kk < 8; ++kk) {
            float4 a0 = *(const float4*)&As[buf][kk][ty];
            float4 a1 = *(const float4*)&As[buf][kk][ty + 4];
            ulonglong2 b0 = *(const ulonglong2*)&Bs[buf][kk][tx];
            ulonglong2 b1 = *(const ulonglong2*)&Bs[buf][kk][tx + 4];
            float av[8] = {a0.x, a0.y, a0.z, a0.w, a1.x, a1.y, a1.z, a1.w};
            unsigned long long bv[4] = {b0.x, b0.y, b1.x, b1.y};
            #pragma unroll
            for (int r = 0; r < 8; ++r) {
                unsigned long long aa = pack2(av[r], av[r]);
                #pragma unroll
                for (int c = 0; c < 4; ++c) ffma2(acc[r][c], aa, bv[c]);
            }
        }
        if (kt + 1 < KT) {
            int nb = buf ^ 1;
            As[nb][kq + 0][lrow] = aN.x * eN.x;
            As[nb][kq + 1][lrow] = aN.y * eN.y;
            As[nb][kq + 2][lrow] = aN.z * eN.z;
            As[nb][kq + 3][lrow] = aN.w * eN.w;
            Bs[nb][kq + 0][lrow] = bN.x;
            Bs[nb][kq + 1][lrow] = bN.y;
            Bs[nb][kq + 2][lrow] = bN.z;
            Bs[nb][kq + 3][lrow] = bN.w;
            __syncthreads();
            buf = nb;
        }
    }

    // epilogue: A_comb = 0.5*adj*(S+1), diagonal -> adj
    #pragma unroll
    for (int r = 0; r < 8; ++r) {
        int gi = iBase + ty + r;
        const float* adjRow = adj_v + (size_t)gi * NN_NODES;
        float* dst = g_Acomb + (size_t)gi * NN_NODES;
        #pragma unroll
        for (int c = 0; c < 4; ++c) {
            int gj = jBase + tx + c * 2;
            float2 s = unpack2(acc[r][c]);
            float adj0 = adjRow[gj];
            float adj1 = adjRow[gj + 1];
            float o0 = (gi == gj)     ? adj0 : 0.5f * adj0 * (s.x + 1.0f);
            float o1 = (gi == gj + 1) ? adj1 : 0.5f * adj1 * (s.y + 1.0f);
            float2 o = make_float2(o0, o1);
            *(float2*)&dst[gj] = o;
        }
    }
}

// ---------------- generic NN GEMM body (row-major A[M,K], B[K,N]) ----------------
__device__ __forceinline__ void gemm_nn_body(
    const float* __restrict__ A, const float* __restrict__ B,
    float* __restrict__ C, int Nn, int K, const float* __restrict__ bias) {
    __shared__ __align__(16) float As[2][8][128];
    __shared__ __align__(16) float Bs[2][8][128];

    const int tid = threadIdx.x;
    const int iBase = blockIdx.y * 128;
    const int jBase = blockIdx.x * 128;

    // A-tile: pair mapping (coalesced 32B per row)
    const int lrow = tid >> 1;
    const int kq   = (tid & 1) * 4;
    const float* Aptr = A + (size_t)(iBase + lrow) * K + kq;

    // B-tile: k = tid/32, n = (tid%32)*4 (fully coalesced)
    const int bk = tid >> 5;
    const int bn = (tid & 31) * 4;
    const float* Bptr = B + (size_t)bk * Nn + jBase + bn;

    unsigned long long acc[8][4];
    #pragma unroll
    for (int r = 0; r < 8; ++r)
        #pragma unroll
        for (int c = 0; c < 4; ++c) acc[r][c] = 0ull;

    {
        float4 a = *(const float4*)Aptr;
        float4 b = *(const float4*)Bptr;
        As[0][kq + 0][lrow] = a.x;
        As[0][kq + 1][lrow] = a.y;
        As[0][kq + 2][lrow] = a.z;
        As[0][kq + 3][lrow] = a.w;
        *(float4*)&Bs[0][bk][bn] = b;
    }
    __syncthreads();

    const int tx = (tid & 15) * 8;
    const int ty = (tid >> 4) * 8;
    int buf = 0;
    const int KT = K / 8;

    for (int kt = 0; kt < KT; ++kt) {
        float4 aN, bN;
        if (kt + 1 < KT) {
            aN = *(const float4*)(Aptr + (size_t)(kt + 1) * 8);
            bN = *(const float4*)(Bptr + (size_t)(kt + 1) * 8 * Nn);
        }
        #pragma unroll
        for (int kk = 0; kk < 8; ++kk) {
            float4 a0 = *(const float4*)&As[buf][kk][ty];
            float4 a1 = *(const float4*)&As[buf][kk][ty + 4];
            ulonglong2 b0 = *(const ulonglong2*)&Bs[buf][kk][tx];
            ulonglong2 b1 = *(const ulonglong2*)&Bs[buf][kk][tx + 4];
            float av[8] = {a0.x, a0.y, a0.z, a0.w, a1.x, a1.y, a1.z, a1.w};
            unsigned long long bv[4] = {b0.x, b0.y, b1.x, b1.y};
            #pragma unroll
            for (int r = 0; r < 8; ++r) {
                unsigned long long aa = pack2(av[r], av[r]);
                #pragma unroll
                for (int c = 0; c < 4; ++c) ffma2(acc[r][c], aa, bv[c]);
            }
        }
        if (kt + 1 < KT) {
            int nb = buf ^ 1;
            As[nb][kq + 0][lrow] = aN.x;
            As[nb][kq + 1][lrow] = aN.y;
            As[nb][kq + 2][lrow] = aN.z;
            As[nb][kq + 3][lrow] = aN.w;
            *(float4*)&Bs[nb][bk][bn] = bN;
            __syncthreads();
            buf = nb;
        }
    }

    #pragma unroll
    for (int r = 0; r < 8; ++r) {
        int gi = iBase + ty + r;
        float* dst = C + (size_t)gi * Nn;
        #pragma unroll
        for (int c = 0; c < 4; ++c) {
            int gj = jBase + tx + c * 2;
            float2 v = unpack2(acc[r][c]);
            if (bias) { v.x += bias[gj]; v.y += bias[gj + 1]; }
            *(float2*)&dst[gj] = v;
        }
    }
}

// K1: HW = H_v @ weight   [4096,512] = [4096,512]@[512,512]
__global__ __launch_bounds__(256, 2) void gemm_hw_kernel(
    const float* __restrict__ Hv, const float* __restrict__ W) {
    gemm_nn_body(Hv, W, g_HW, DIM_OUT, DIM_V, nullptr);
}

// K3: ret = A_comb @ HW + bias   [4096,512] = [4096,4096]@[4096,512]
__global__ __launch_bounds__(256, 2) void gemm_out_kernel(
    const float* __restrict__ bias, float* __restrict__ out) {
    gemm_nn_body(g_Acomb, g_HW, out, DIM_OUT, NN_NODES, bias);
}

extern "C" void kernel_launch(void* const* d_in, const int* in_sizes, int n_in,
                              void* d_out, int out_size) {
    const float* H_v    = (const float*)d_in[0];
    const float* H_e    = (const float*)d_in[1];
    // d_in[2] = adj_e : unused by the node_layer path
    const float* adj_v  = (const float*)d_in[3];
    const float* T      = (const float*)d_in[4];
    const float* weight = (const float*)d_in[5];
    const float* p      = (const float*)d_in[6];
    const float* bias   = (const float*)d_in[7];
    float* out = (float*)d_out;
    (void)in_sizes; (void)n_in;

    // K0: edge scaling vector
    escale_kernel<<<NN_EDGES / 8, dim3(32, 8)>>>(H_e, p);

    // K1: HW = H_v @ W (independent of K0/K2)
    gemm_hw_kernel<<<dim3(DIM_OUT / 128, NN_NODES / 128), 256>>>(H_v, weight);

    // K2: dominant GEMM  S=(T*e)@T^T with fused A_comb epilogue
    gemm1_kernel<<<dim3(NN_NODES / 128, NN_NODES / 128), 256>>>(T, adj_v);

    // K3: ret = A_comb @ HW + bias
    gemm_out_kernel<<<dim3(DIM_OUT / 128, NN_NODES / 128), 256>>>(bias, out);

    // Tuple output: (ret, H_e). Copy H_e into the tail if the harness expects it.
    const size_t ret_elems = (size_t)NN_NODES * DIM_OUT;
    const size_t he_elems  = (size_t)NN_EDGES * DIM_E;
    if ((size_t)out_size >= ret_elems + he_elems) {
        cudaMemcpyAsync(out + ret_elems, H_e, he_elems * sizeof(float),
                        cudaMemcpyDeviceToDevice);
    }
}

// round 4
// speedup vs baseline: 2.0783x; 2.0783x over previous
#include <cuda_runtime.h>
#include <cuda_bf16.h>

// Problem constants
#define NN_NODES 4096
#define NN_EDGES 8192
#define DIM_V    512
#define DIM_OUT  512
#define DIM_E    128

// ---------------- scratch (device globals; no allocation allowed) ----------------
__device__ float g_e_scale[NN_EDGES];
__device__ float g_Acomb[(size_t)NN_NODES * NN_NODES];            // 64 MB fp32
__device__ float g_HW[(size_t)NN_NODES * DIM_OUT];                //  8 MB
__device__ __nv_bfloat16 g_Ah[(size_t)NN_NODES * NN_EDGES];       // 64 MB
__device__ __nv_bfloat16 g_Al[(size_t)NN_NODES * NN_EDGES];       // 64 MB
__device__ __nv_bfloat16 g_Bh[(size_t)NN_NODES * NN_EDGES];       // 64 MB
__device__ __nv_bfloat16 g_Bl[(size_t)NN_NODES * NN_EDGES];       // 64 MB

// ---------------- cp.async helpers (non-'a' features only) ----------------
__device__ __forceinline__ unsigned smem_u32(const void* p) {
    unsigned a;
    asm("{ .reg .u64 t; cvta.to.shared.u64 t, %1; cvt.u32.u64 %0, t; }" : "=r"(a) : "l"(p));
    return a;
}
#define CP_ASYNC8(dst, src) \
    asm volatile("cp.async.ca.shared.global [%0], [%1], 8;" :: "r"(dst), "l"(src) : "memory")
#define CP_COMMIT() asm volatile("cp.async.commit_group;" ::: "memory")
#define CP_WAIT(n)  asm volatile("cp.async.wait_group %0;" :: "n"(n) : "memory")

#define MMA_BF16(acc, A, B) \
    asm volatile("mma.sync.aligned.m16n8k16.row.col.f32.bf16.bf16.f32 " \
                 "{%0,%1,%2,%3},{%4,%5,%6,%7},{%8,%9},{%0,%1,%2,%3};" \
                 : "+f"((acc)[0]), "+f"((acc)[1]), "+f"((acc)[2]), "+f"((acc)[3]) \
                 : "r"((A)[0]), "r"((A)[1]), "r"((A)[2]), "r"((A)[3]), \
                   "r"((B)[0]), "r"((B)[1]))

// ---------------- packed f32x2 helpers (SIMT GEMMs) ----------------
__device__ __forceinline__ void ffma2(unsigned long long& d,
                                      unsigned long long a,
                                      unsigned long long b) {
    asm("fma.rn.f32x2 %0, %1, %2, %0;" : "+l"(d) : "l"(a), "l"(b));
}
__device__ __forceinline__ unsigned long long pack2(float x, float y) {
    unsigned long long r;
    asm("mov.b64 %0, {%1, %2};" : "=l"(r) : "f"(x), "f"(y));
    return r;
}
__device__ __forceinline__ float2 unpack2(unsigned long long v) {
    float2 f;
    asm("mov.b64 {%0, %1}, %2;" : "=f"(f.x), "=f"(f.y) : "l"(v));
    return f;
}

// ---------------- K0: e_scale[e] = dot(H_e[e,:], p) ----------------
__global__ void escale_kernel(const float* __restrict__ He,
                              const float* __restrict__ p) {
    int row  = blockIdx.x * 8 + threadIdx.y;
    int lane = threadIdx.x;
    float4 h  = ((const float4*)(He + (size_t)row * DIM_E))[lane];
    float4 pv = ((const float4*)p)[lane];
    float v = h.x * pv.x + h.y * pv.y + h.z * pv.z + h.w * pv.w;
    #pragma unroll
    for (int o = 16; o; o >>= 1) v += __shfl_xor_sync(0xffffffffu, v, o);
    if (lane == 0) g_e_scale[row] = v;
}

// ---------------- K-split: T -> (Bh,Bl), T*e -> (Ah,Al) bf16 hi/lo ----------------
__global__ __launch_bounds__(256) void split_kernel(const float* __restrict__ T) {
    size_t i = ((size_t)blockIdx.x * 256 + threadIdx.x) * 4;
    unsigned col = (unsigned)(i & (NN_EDGES - 1));
    float4 t = *(const float4*)(T + i);
    float4 e = *(const float4*)(g_e_scale + col);

    float b[4] = {t.x, t.y, t.z, t.w};
    float a[4] = {t.x * e.x, t.y * e.y, t.z * e.z, t.w * e.w};

    unsigned long long bh = 0, bl = 0, ah = 0, al = 0;
    #pragma unroll
    for (int k = 0; k < 4; ++k) {
        __nv_bfloat16 h = __float2bfloat16(b[k]);
        __nv_bfloat16 l = __float2bfloat16(b[k] - __bfloat162float(h));
        bh |= (unsigned long long)__bfloat16_as_ushort(h) << (16 * k);
        bl |= (unsigned long long)__bfloat16_as_ushort(l) << (16 * k);
        h = __float2bfloat16(a[k]);
        l = __float2bfloat16(a[k] - __bfloat162float(h));
        ah |= (unsigned long long)__bfloat16_as_ushort(h) << (16 * k);
        al |= (unsigned long long)__bfloat16_as_ushort(l) << (16 * k);
    }
    *(unsigned long long*)(g_Bh + i) = bh;
    *(unsigned long long*)(g_Bl + i) = bl;
    *(unsigned long long*)(g_Ah + i) = ah;
    *(unsigned long long*)(g_Al + i) = al;
}

// ---------------- K2: mma.sync split-bf16 GEMM1 with fused epilogue ----------------
// S = A @ B^T (A=T*e, B=T, both bf16 hi/lo), A_comb = (i==j) ? adj : 0.5*adj*(S+1)
// CTA tile 128x128, K-chunk 32, double-buffered cp.async.
// SMEM tiles: [128 rows][32 bf16] padded to 72B rows (conflict-free frag loads).
#define ROWB 72u                     // bytes per smem row (64 data + 8 pad)
#define TILEB (128u * ROWB)          // 9216 B per tile
#define STAGEB (4u * TILEB)          // 36864 B per stage (Ah,Al,Bh,Bl)
#define SMEM_G1 (2u * STAGEB)        // 73728 B
#define OFF_AH(s) ((unsigned)(s) * STAGEB)
#define OFF_AL(s) (OFF_AH(s) + TILEB)
#define OFF_BH(s) (OFF_AH(s) + 2u * TILEB)
#define OFF_BL(s) (OFF_AH(s) + 3u * TILEB)
#define NCHUNK (NN_EDGES / 32)       // 256

__global__ __launch_bounds__(256) void gemm1_mma_kernel(const float* __restrict__ adj_v) {
    extern __shared__ char sm[];
    const unsigned sb = smem_u32(sm);
    const int tid  = threadIdx.x;
    const int warp = tid >> 5;
    const int lane = tid & 31;
    const int g = lane >> 2, t = lane & 3;
    const int iBase = blockIdx.y * 128;
    const int jBase = blockIdx.x * 128;
    const int wM = (warp >> 1) * 32;     // warp row origin (4 warps over M)
    const int wN = (warp & 1) * 64;      // warp col origin (2 warps over N)

    float acc[2][8][4];
    #pragma unroll
    for (int mt = 0; mt < 2; ++mt)
        #pragma unroll
        for (int nt = 0; nt < 8; ++nt)
            #pragma unroll
            for (int q = 0; q < 4; ++q) acc[mt][nt][q] = 0.0f;

    // -------- fill stage stg with K-chunk 'chunk' --------
    auto fill = [&](int chunk, int stg) {
        const unsigned kb = (unsigned)chunk * 32u;
        #pragma unroll
        for (int i = 0; i < 4; ++i) {
            int c = tid + i * 256;
            int row = c >> 3, sub = c & 7;          // 8x 8B segments per 64B row
            unsigned so = (unsigned)row * ROWB + (unsigned)sub * 8u;
            size_t ga = (size_t)(iBase + row) * NN_EDGES + kb + sub * 4;
            size_t gb = (size_t)(jBase + row) * NN_EDGES + kb + sub * 4;
            CP_ASYNC8(sb + OFF_AH(stg) + so, (const char*)(g_Ah + ga));
            CP_ASYNC8(sb + OFF_AL(stg) + so, (const char*)(g_Al + ga));
            CP_ASYNC8(sb + OFF_BH(stg) + so, (const char*)(g_Bh + gb));
            CP_ASYNC8(sb + OFF_BL(stg) + so, (const char*)(g_Bl + gb));
        }
        CP_COMMIT();
    };

    fill(0, 0);

    for (int c = 0; c < NCHUNK; ++c) {
        const int s = c & 1;
        if (c + 1 < NCHUNK) { fill(c + 1, s ^ 1); CP_WAIT(1); }
        else                { CP_WAIT(0); }
        __syncthreads();

        const char* pAH = sm + OFF_AH(s);
        const char* pAL = sm + OFF_AL(s);
        const char* pBH = sm + OFF_BH(s);
        const char* pBL = sm + OFF_BL(s);

        #pragma unroll
        for (int ks = 0; ks < 2; ++ks) {
            unsigned ah[2][4], al[2][4], bh[8][2], bl[8][2];
            const unsigned colb = (unsigned)(ks * 32 + t * 4);
            #pragma unroll
            for (int mt = 0; mt < 2; ++mt) {
                unsigned o0 = (unsigned)(wM + mt * 16 + g) * ROWB + colb;
                unsigned o1 = o0 + 8u * ROWB;
                ah[mt][0] = *(const unsigned*)(pAH + o0);
                ah[mt][1] = *(const unsigned*)(pAH + o1);
                ah[mt][2] = *(const unsigned*)(pAH + o0 + 16u);
                ah[mt][3] = *(const unsigned*)(pAH + o1 + 16u);
                al[mt][0] = *(const unsigned*)(pAL + o0);
                al[mt][1] = *(const unsigned*)(pAL + o1);
                al[mt][2] = *(const unsigned*)(pAL + o0 + 16u);
                al[mt][3] = *(const unsigned*)(pAL + o1 + 16u);
            }
            #pragma unroll
            for (int nt = 0; nt < 8; ++nt) {
                unsigned ob = (unsigned)(wN + nt * 8 + g) * ROWB + colb;
                bh[nt][0] = *(const unsigned*)(pBH + ob);
                bh[nt][1] = *(const unsigned*)(pBH + ob + 16u);
                bl[nt][0] = *(const unsigned*)(pBL + ob);
                bl[nt][1] = *(const unsigned*)(pBL + ob + 16u);
            }
            #pragma unroll
            for (int mt = 0; mt < 2; ++mt)
                #pragma unroll
                for (int nt = 0; nt < 8; ++nt) {
                    MMA_BF16(acc[mt][nt], ah[mt], bh[nt]);
                    MMA_BF16(acc[mt][nt], ah[mt], bl[nt]);
                    MMA_BF16(acc[mt][nt], al[mt], bh[nt]);
                }
        }
        __syncthreads();
    }

    // -------- epilogue: A_comb = 0.5*adj*(S+1), diagonal -> adj --------
    #pragma unroll
    for (int mt = 0; mt < 2; ++mt) {
        int gi0 = iBase + wM + mt * 16 + g;        // rows gi0 and gi0+8
        const float* adj0 = adj_v + (size_t)gi0 * NN_NODES;
        const float* adj1 = adj0 + 8u * NN_NODES;
        float* d0 = g_Acomb + (size_t)gi0 * NN_NODES;
        float* d1 = d0 + 8u * NN_NODES;
        #pragma unroll
        for (int nt = 0; nt < 8; ++nt) {
            int gj = jBase + wN + nt * 8 + t * 2;
            float2 a0 = *(const float2*)(adj0 + gj);
            float2 a1 = *(const float2*)(adj1 + gj);
            float2 o0, o1;
            o0.x = (gi0 == gj)         ? a0.x : 0.5f * a0.x * (acc[mt][nt][0] + 1.0f);
            o0.y = (gi0 == gj + 1)     ? a0.y : 0.5f * a0.y * (acc[mt][nt][1] + 1.0f);
            o1.x = (gi0 + 8 == gj)     ? a1.x : 0.5f * a1.x * (acc[mt][nt][2] + 1.0f);
            o1.y = (gi0 + 8 == gj + 1) ? a1.y : 0.5f * a1.y * (acc[mt][nt][3] + 1.0f);
            *(float2*)(d0 + gj) = o0;
            *(float2*)(d1 + gj) = o1;
        }
    }
}

// ---------------- generic SIMT NN GEMM (row-major A[M,K], B[K,N]) ----------------
__device__ __forceinline__ void gemm_nn_body(
    const float* __restrict__ A, const float* __restrict__ B,
    float* __restrict__ C, int Nn, int K, const float* __restrict__ bias) {
    __shared__ __align__(16) float As[2][8][128];
    __shared__ __align__(16) float Bs[2][8][128];

    const int tid = threadIdx.x;
    const int iBase = blockIdx.y * 128;
    const int jBase = blockIdx.x * 128;

    const int lrow = tid >> 1;
    const int kq   = (tid & 1) * 4;
    const float* Aptr = A + (size_t)(iBase + lrow) * K + kq;

    const int bk = tid >> 5;
    const int bn = (tid & 31) * 4;
    const float* Bptr = B + (size_t)bk * Nn + jBase + bn;

    unsigned long long acc[8][4];
    #pragma unroll
    for (int r = 0; r < 8; ++r)
        #pragma unroll
        for (int c = 0; c < 4; ++c) acc[r][c] = 0ull;

    {
        float4 a = *(const float4*)Aptr;
        float4 b = *(const float4*)Bptr;
        As[0][kq + 0][lrow] = a.x;
        As[0][kq + 1][lrow] = a.y;
        As[0][kq + 2][lrow] = a.z;
        As[0][kq + 3][lrow] = a.w;
        *(float4*)&Bs[0][bk][bn] = b;
    }
    __syncthreads();

    const int tx = (tid & 15) * 8;
    const int ty = (tid >> 4) * 8;
    int buf = 0;
    const int KT = K / 8;

    for (int kt = 0; kt < KT; ++kt) {
        float4 aN, bN;
        if (kt + 1 < KT) {
            aN = *(const float4*)(Aptr + (size_t)(kt + 1) * 8);
            bN = *(const float4*)(Bptr + (size_t)(kt + 1) * 8 * Nn);
        }
        #pragma unroll
        for (int kk = 0; kk < 8; ++kk) {
            float4 a0 = *(const float4*)&As[buf][kk][ty];
            float4 a1 = *(const float4*)&As[buf][kk][ty + 4];
            ulonglong2 b0 = *(const ulonglong2*)&Bs[buf][kk][tx];
            ulonglong2 b1 = *(const ulonglong2*)&Bs[buf][kk][tx + 4];
            float av[8] = {a0.x, a0.y, a0.z, a0.w, a1.x, a1.y, a1.z, a1.w};
            unsigned long long bv[4] = {b0.x, b0.y, b1.x, b1.y};
            #pragma unroll
            for (int r = 0; r < 8; ++r) {
                unsigned long long aa = pack2(av[r], av[r]);
                #pragma unroll
                for (int c = 0; c < 4; ++c) ffma2(acc[r][c], aa, bv[c]);
            }
        }
        if (kt + 1 < KT) {
            int nb = buf ^ 1;
            As[nb][kq + 0][lrow] = aN.x;
            As[nb][kq + 1][lrow] = aN.y;
            As[nb][kq + 2][lrow] = aN.z;
            As[nb][kq + 3][lrow] = aN.w;
            *(float4*)&Bs[nb][bk][bn] = bN;
            __syncthreads();
            buf = nb;
        }
    }

    #pragma unroll
    for (int r = 0; r < 8; ++r) {
        int gi = iBase + ty + r;
        float* dst = C + (size_t)gi * Nn;
        #pragma unroll
        for (int c = 0; c < 4; ++c) {
            int gj = jBase + tx + c * 2;
            float2 v = unpack2(acc[r][c]);
            if (bias) { v.x += bias[gj]; v.y += bias[gj + 1]; }
            *(float2*)&dst[gj] = v;
        }
    }
}

__global__ __launch_bounds__(256, 2) void gemm_hw_kernel(
    const float* __restrict__ Hv, const float* __restrict__ W) {
    gemm_nn_body(Hv, W, g_HW, DIM_OUT, DIM_V, nullptr);
}

__global__ __launch_bounds__(256, 2) void gemm_out_kernel(
    const float* __restrict__ bias, float* __restrict__ out) {
    gemm_nn_body(g_Acomb, g_HW, out, DIM_OUT, NN_NODES, bias);
}

extern "C" void kernel_launch(void* const* d_in, const int* in_sizes, int n_in,
                              void* d_out, int out_size) {
    const float* H_v    = (const float*)d_in[0];
    const float* H_e    = (const float*)d_in[1];
    const float* adj_v  = (const float*)d_in[3];
    const float* T      = (const float*)d_in[4];
    const float* weight = (const float*)d_in[5];
    const float* p      = (const float*)d_in[6];
    const float* bias   = (const float*)d_in[7];
    float* out = (float*)d_out;
    (void)in_sizes; (void)n_in;

    cudaFuncSetAttribute(gemm1_mma_kernel,
                         cudaFuncAttributeMaxDynamicSharedMemorySize, SMEM_G1);

    // K0: edge scaling vector
    escale_kernel<<<NN_EDGES / 8, dim3(32, 8)>>>(H_e, p);

    // K-split: bf16 hi/lo operand prep (depends on K0)
    split_kernel<<<(NN_NODES * NN_EDGES) / (256 * 4), 256>>>(T);

    // K1: HW = H_v @ W
    gemm_hw_kernel<<<dim3(DIM_OUT / 128, NN_NODES / 128), 256>>>(H_v, weight);

    // K2: dominant GEMM via mma.sync split-bf16 (3 products)
    gemm1_mma_kernel<<<dim3(NN_NODES / 128, NN_NODES / 128), 256, SMEM_G1>>>(adj_v);

    // K3: ret = A_comb @ HW + bias
    gemm_out_kernel<<<dim3(DIM_OUT / 128, NN_NODES / 128), 256>>>(bias, out);

    const size_t ret_elems = (size_t)NN_NODES * DIM_OUT;
    const size_t he_elems  = (size_t)NN_EDGES * DIM_E;
    if ((size_t)out_size >= ret_elems + he_elems) {
        cudaMemcpyAsync(out + ret_elems, H_e, he_elems * sizeof(float),
                        cudaMemcpyDeviceToDevice);
    }
}